// round 14
// baseline (speedup 1.0000x reference)
#include <cuda_runtime.h>
#include <cuda_fp16.h>
#include <math.h>
#include <stdint.h>

#define N_NODES 100000
#define N_EDGES 3200000
#define K1 489
#define GEMM1_BLOCKS ((N_NODES + 127) / 128)   // 782

// ---------------- scratch (device globals; no allocation allowed) ----------
__device__ __align__(256) __half g_p1h[N_NODES * 64];   // fp16 messages L1
__device__ __align__(256) __half g_p2h[N_NODES * 32];   // fp16 messages L2
__device__ __align__(256) float  g_p3[N_NODES * 2];
__device__ float g_dinv[N_NODES];

// CSR (incoming edges, unordered row placement)
__device__ int g_cnt[N_NODES];
__device__ int g_start[N_NODES];
__device__ int g_cursor[N_NODES];
__device__ int g_head;
__device__ int g_csr[N_EDGES];

// ---------------- f32x2 packed-FMA helpers ----------------------------------
__device__ __forceinline__ void fma2(unsigned long long& d,
                                     unsigned long long a,
                                     unsigned long long b) {
    asm("fma.rn.f32x2 %0, %1, %2, %0;" : "+l"(d) : "l"(a), "l"(b));
}
__device__ __forceinline__ unsigned long long splat2(float v) {
    unsigned long long r;
    asm("mov.b64 %0, {%1, %1};" : "=l"(r) : "f"(v));
    return r;
}
__device__ __forceinline__ float2 unpack2(unsigned long long v) {
    float2 r;
    asm("mov.b64 {%0, %1}, %2;" : "=f"(r.x), "=f"(r.y) : "l"(v));
    return r;
}
// unpack one uint4 = 8 halves (4 half2) and accumulate into 8 fp32
__device__ __forceinline__ void acc_h8(float* a, uint4 v) {
    const __half2* h = (const __half2*)&v;
#pragma unroll
    for (int i = 0; i < 4; i++) {
        float2 f = __half22float2(h[i]);
        a[2 * i]     += f.x;
        a[2 * i + 1] += f.y;
    }
}

// ---------------- CSR build (head) ------------------------------------------
__global__ void k_init() {
    int i = blockIdx.x * blockDim.x + threadIdx.x;
    if (i < N_NODES) g_cnt[i] = 0;
    if (i == 0) g_head = 0;
}

__global__ void k_cnt(const int* __restrict__ dst) {
    int e = blockIdx.x * blockDim.x + threadIdx.x;
    if (e < N_EDGES) atomicAdd(&g_cnt[dst[e]], 1);
}

__global__ void k_alloc() {
    int i = blockIdx.x * blockDim.x + threadIdx.x;
    if (i >= N_NODES) return;
    int c = g_cnt[i];
    int s = atomicAdd(&g_head, c);
    g_start[i]  = s;
    g_cursor[i] = s;
    g_dinv[i]   = rsqrtf((float)(c + 1));   // +1 self loop
}

// ---------------- fused: GEMM1 (f32x2, 8x4 microtile) + CSR-fill ------------
// blocks [0, GEMM1_BLOCKS)      : p1h = fp16(dinv .* (x @ W1))
// blocks [GEMM1_BLOCKS, +12500) : csr fill
__global__ __launch_bounds__(256) void k_gemm1_fill(const float* __restrict__ X,
                                                    const float* __restrict__ W,
                                                    const int* __restrict__ src,
                                                    const int* __restrict__ dst) {
    const int tid = threadIdx.x;

    if (blockIdx.x >= GEMM1_BLOCKS) {
        int e = (blockIdx.x - GEMM1_BLOCKS) * 256 + tid;
        if (e < N_EDGES) {
            int d = dst[e];
            int pos = atomicAdd(&g_cursor[d], 1);
            g_csr[pos] = src[e];
        }
        return;
    }

    // ---- GEMM1: 128x64 tile, 8m x 4n microtile (m in f32x2 pairs), BK=16 ----
    __shared__ float Xs[16][132];   // [k][m] padded
    __shared__ float Ws[16][64];    // [k][n]
    const int tx = tid & 15;
    const int ty = tid >> 4;
    const int blockM = blockIdx.x * 128;

    unsigned long long acc2[4][4] = {};   // [m-pair][n]

    for (int k0 = 0; k0 < K1; k0 += 16) {
#pragma unroll
        for (int i = 0; i < 8; i++) {
            int e  = tid + i * 256;
            int kl = e & 15, ml = e >> 4;
            int r = blockM + ml, k = k0 + kl;
            Xs[kl][ml] = (r < N_NODES && k < K1) ? X[(long long)r * K1 + k] : 0.f;
        }
        {
            int kl = tid >> 4, nl = (tid & 15) * 4;
            int k = k0 + kl;
            float4 w = (k < K1) ? *(const float4*)&W[k * 64 + nl]
                                : make_float4(0.f, 0.f, 0.f, 0.f);
            *(float4*)&Ws[kl][nl] = w;
        }
        __syncthreads();
#pragma unroll
        for (int kk = 0; kk < 16; kk++) {
            unsigned long long xp[4];
            *(float4*)&xp[0] = *(const float4*)&Xs[kk][ty * 8];
            *(float4*)&xp[2] = *(const float4*)&Xs[kk][ty * 8 + 4];
            float4 wv = *(const float4*)&Ws[kk][tx * 4];
            unsigned long long ws0 = splat2(wv.x), ws1 = splat2(wv.y);
            unsigned long long ws2 = splat2(wv.z), ws3 = splat2(wv.w);
#pragma unroll
            for (int ip = 0; ip < 4; ip++) {
                fma2(acc2[ip][0], xp[ip], ws0);
                fma2(acc2[ip][1], xp[ip], ws1);
                fma2(acc2[ip][2], xp[ip], ws2);
                fma2(acc2[ip][3], xp[ip], ws3);
            }
        }
        __syncthreads();
    }

    // epilogue: unpack m-pairs, scale by dinv, convert fp16, store 4 cols
#pragma unroll
    for (int ip = 0; ip < 4; ip++) {
        int r0 = blockM + ty * 8 + ip * 2;
        int r1 = r0 + 1;
        float2 c0 = unpack2(acc2[ip][0]);
        float2 c1 = unpack2(acc2[ip][1]);
        float2 c2 = unpack2(acc2[ip][2]);
        float2 c3 = unpack2(acc2[ip][3]);
        if (r0 < N_NODES) {
            float s = g_dinv[r0];
            __half2 h[2];
            h[0] = __floats2half2_rn(c0.x * s, c1.x * s);
            h[1] = __floats2half2_rn(c2.x * s, c3.x * s);
            *(uint2*)&g_p1h[(long long)r0 * 64 + tx * 4] = *(uint2*)h;
        }
        if (r1 < N_NODES) {
            float s = g_dinv[r1];
            __half2 h[2];
            h[0] = __floats2half2_rn(c0.y * s, c1.y * s);
            h[1] = __floats2half2_rn(c2.y * s, c3.y * s);
            *(uint2*)&g_p1h[(long long)r1 * 64 + tx * 4] = *(uint2*)h;
        }
    }
}

// ---------------- fused gather64 + GEMM2 -------------------------------------
// 8 lanes per node; lane g owns 8 features. After aggregation, computes
// p2 = dinv .* (relu(dinv.*a1 + b1) @ W2) in-register with a split butterfly
// reduction; lane g writes output columns 4g..4g+3.
__global__ __launch_bounds__(256) void k_gather64_gemm2(const float* __restrict__ W2,
                                                        const float* __restrict__ b1) {
    __shared__ float Ws2[64 * 32];
    __shared__ float bs[64];
    {
        int tid = threadIdx.x;
        for (int i = tid; i < 64 * 32; i += 256) Ws2[i] = W2[i];
        if (tid < 64) bs[tid] = b1[tid];
    }
    __syncthreads();

    int t = blockIdx.x * blockDim.x + threadIdx.x;
    int node = t >> 3, g = t & 7;
    // exactly 100000*8 threads launched; no tail, all lanes active

    const uint4* P = (const uint4*)g_p1h;   // 8 uint4 per node row

    float a[8] = {};
    acc_h8(a, P[node * 8 + g]);             // self loop
    int beg = g_start[node], n = g_cnt[node];
    int j = 0;
    for (; j + 4 <= n; j += 4) {
        int s0 = g_csr[beg + j],     s1 = g_csr[beg + j + 1];
        int s2 = g_csr[beg + j + 2], s3 = g_csr[beg + j + 3];
        uint4 u0 = __ldg(P + s0 * 8 + g);
        uint4 u1 = __ldg(P + s1 * 8 + g);
        uint4 u2 = __ldg(P + s2 * 8 + g);
        uint4 u3 = __ldg(P + s3 * 8 + g);
        acc_h8(a, u0); acc_h8(a, u1); acc_h8(a, u2); acc_h8(a, u3);
    }
    for (; j < n; j++)
        acc_h8(a, __ldg(P + g_csr[beg + j] * 8 + g));

    // ---- fused GEMM2 ----
    float dv = g_dinv[node];
    int kb = g * 8;
    float part[32];
#pragma unroll
    for (int q = 0; q < 32; q++) part[q] = 0.f;
#pragma unroll
    for (int i = 0; i < 8; i++) {
        float h = fmaxf(fmaf(dv, a[i], bs[kb + i]), 0.f);
        const float4* w4 = (const float4*)&Ws2[(kb + i) * 32];
#pragma unroll
        for (int q = 0; q < 8; q++) {
            float4 w = w4[q];
            part[q * 4 + 0] = fmaf(h, w.x, part[q * 4 + 0]);
            part[q * 4 + 1] = fmaf(h, w.y, part[q * 4 + 1]);
            part[q * 4 + 2] = fmaf(h, w.z, part[q * 4 + 2]);
            part[q * 4 + 3] = fmaf(h, w.w, part[q * 4 + 3]);
        }
    }
    // split butterfly reduction across the 8-lane group
    {
        int send = (g & 4) ? 0 : 16, keep = (g & 4) ? 16 : 0;
#pragma unroll
        for (int i = 0; i < 16; i++) {
            float v = __shfl_xor_sync(0xffffffffu, part[send + i], 4, 8);
            part[i] = part[keep + i] + v;
        }
    }
    {
        int send = (g & 2) ? 0 : 8, keep = (g & 2) ? 8 : 0;
#pragma unroll
        for (int i = 0; i < 8; i++) {
            float v = __shfl_xor_sync(0xffffffffu, part[send + i], 2, 8);
            part[i] = part[keep + i] + v;
        }
    }
    {
        int send = (g & 1) ? 0 : 4, keep = (g & 1) ? 4 : 0;
#pragma unroll
        for (int i = 0; i < 4; i++) {
            float v = __shfl_xor_sync(0xffffffffu, part[send + i], 1, 8);
            part[i] = part[keep + i] + v;
        }
    }
    // lane g holds output columns 4g..4g+3
    __half2 h2[2];
    h2[0] = __floats2half2_rn(part[0] * dv, part[1] * dv);
    h2[1] = __floats2half2_rn(part[2] * dv, part[3] * dv);
    *(uint2*)&g_p2h[(long long)node * 32 + g * 4] = *(uint2*)h2;
}

// ---------------- fused gather32 (fp16 msgs) + GEMM3 ------------------------
// 4 lanes per node; each lane owns one uint4 = 8 features.
__global__ __launch_bounds__(256) void k_gather32_gemm3(const float* __restrict__ W3,
                                                        const float* __restrict__ b2) {
    __shared__ float w3[64];
    __shared__ float bb[32];
    if (threadIdx.x < 64) w3[threadIdx.x] = W3[threadIdx.x];
    if (threadIdx.x < 32) bb[threadIdx.x] = b2[threadIdx.x];
    __syncthreads();

    int t = blockIdx.x * blockDim.x + threadIdx.x;
    int node = t >> 2, lane = t & 3;
    if (node >= N_NODES) return;
    const uint4* P = (const uint4*)g_p2h;   // 4 uint4 per node row

    float a[8] = {};
    acc_h8(a, P[node * 4 + lane]);          // self loop
    int beg = g_start[node], n = g_cnt[node];
    int j = 0;
    for (; j + 4 <= n; j += 4) {
        int s0 = g_csr[beg + j],     s1 = g_csr[beg + j + 1];
        int s2 = g_csr[beg + j + 2], s3 = g_csr[beg + j + 3];
        uint4 u0 = __ldg(P + s0 * 4 + lane);
        uint4 u1 = __ldg(P + s1 * 4 + lane);
        uint4 u2 = __ldg(P + s2 * 4 + lane);
        uint4 u3 = __ldg(P + s3 * 4 + lane);
        acc_h8(a, u0); acc_h8(a, u1); acc_h8(a, u2); acc_h8(a, u3);
    }
    for (; j < n; j++)
        acc_h8(a, __ldg(P + g_csr[beg + j] * 4 + lane));

    float dv = g_dinv[node];
    int kb = lane * 8;
    float acc0 = 0.f, acc1 = 0.f;
#pragma unroll
    for (int i = 0; i < 8; i++) {
        float h = fmaxf(fmaf(dv, a[i], bb[kb + i]), 0.f);
        acc0 = fmaf(h, w3[(kb + i) * 2],     acc0);
        acc1 = fmaf(h, w3[(kb + i) * 2 + 1], acc1);
    }
#pragma unroll
    for (int off = 2; off > 0; off >>= 1) {
        acc0 += __shfl_down_sync(0xffffffffu, acc0, off, 4);
        acc1 += __shfl_down_sync(0xffffffffu, acc1, off, 4);
    }
    if (lane == 0)
        ((float2*)g_p3)[node] = make_float2(acc0 * dv, acc1 * dv);
}

// ---------------- fused gather2 + log_softmax -------------------------------
__global__ __launch_bounds__(256) void k_gather2_out(const float* __restrict__ b3,
                                                     float* __restrict__ out) {
    int node = blockIdx.x * blockDim.x + threadIdx.x;
    if (node >= N_NODES) return;
    const float2* P = (const float2*)g_p3;
    float2 v = P[node];   // self loop
    int beg = g_start[node], n = g_cnt[node];
    int j = 0;
    for (; j + 4 <= n; j += 4) {
        int s0 = g_csr[beg + j],     s1 = g_csr[beg + j + 1];
        int s2 = g_csr[beg + j + 2], s3 = g_csr[beg + j + 3];
        float2 u0 = __ldg(P + s0), u1 = __ldg(P + s1);
        float2 u2 = __ldg(P + s2), u3 = __ldg(P + s3);
        v.x += (u0.x + u1.x) + (u2.x + u3.x);
        v.y += (u0.y + u1.y) + (u2.y + u3.y);
    }
    for (; j < n; j++) {
        float2 u = __ldg(P + g_csr[beg + j]);
        v.x += u.x; v.y += u.y;
    }
    float dv = g_dinv[node];
    float z0 = fmaf(dv, v.x, __ldg(&b3[0]));
    float z1 = fmaf(dv, v.y, __ldg(&b3[1]));
    float m = fmaxf(z0, z1);
    float lse = m + logf(expf(z0 - m) + expf(z1 - m));
    ((float2*)out)[node] = make_float2(z0 - lse, z1 - lse);
}

// ---------------- launch ----------------------------------------------------
extern "C" void kernel_launch(void* const* d_in, const int* in_sizes, int n_in,
                              void* d_out, int out_size) {
    const float* x  = (const float*)d_in[0];
    const int*   ei = (const int*)d_in[1];
    const float* W1 = (const float*)d_in[2];
    const float* b1 = (const float*)d_in[3];
    const float* W2 = (const float*)d_in[4];
    const float* b2 = (const float*)d_in[5];
    const float* W3 = (const float*)d_in[6];
    const float* b3 = (const float*)d_in[7];
    float* out = (float*)d_out;

    const int* src = ei;
    const int* dst = ei + N_EDGES;

    const int TB = 256;
    const int gN = (N_NODES + TB - 1) / TB;
    const int gE = (N_EDGES + TB - 1) / TB;   // 12500

    // CSR head
    k_init<<<gN, TB>>>();
    k_cnt<<<gE, TB>>>(dst);
    k_alloc<<<gN, TB>>>();

    // layer 1 GEMM (f32x2) overlapped with CSR fill
    k_gemm1_fill<<<GEMM1_BLOCKS + gE, TB>>>(x, W1, src, dst);

    // layer 1 aggregation + layer 2 GEMM (fused)
    k_gather64_gemm2<<<(N_NODES * 8) / TB, TB>>>(W2, b1);

    // layer 3 (gather32 + gemm3 fused, fp16 messages)
    k_gather32_gemm3<<<(N_NODES * 4 + TB - 1) / TB, TB>>>(W3, b2);

    // output (gather2 + log_softmax fused)
    k_gather2_out<<<gN, TB>>>(b3, out);
}

// round 15
// speedup vs baseline: 1.4090x; 1.4090x over previous
#include <cuda_runtime.h>
#include <cuda_fp16.h>
#include <math.h>
#include <stdint.h>

#define N_NODES 100000
#define N_EDGES 3200000
#define K1 489
#define GEMM1_BLOCKS ((N_NODES + 127) / 128)   // 782

// ---------------- scratch (device globals; no allocation allowed) ----------
__device__ __align__(256) __half g_p1h[N_NODES * 64];   // fp16 messages L1
__device__ __align__(256) __half g_p2h[N_NODES * 32];   // fp16 messages L2
__device__ __align__(256) float  g_p3[N_NODES * 2];
__device__ float g_dinv[N_NODES];

// CSR (incoming edges, unordered row placement)
__device__ int g_cnt[N_NODES];
__device__ int g_start[N_NODES];
__device__ int g_cursor[N_NODES];
__device__ int g_head;
__device__ int g_csr[N_EDGES];

// ---------------- f32x2 packed-FMA helpers ----------------------------------
__device__ __forceinline__ void fma2(unsigned long long& d,
                                     unsigned long long a,
                                     unsigned long long b) {
    asm("fma.rn.f32x2 %0, %1, %2, %0;" : "+l"(d) : "l"(a), "l"(b));
}
__device__ __forceinline__ unsigned long long splat2(float v) {
    unsigned long long r;
    asm("mov.b64 %0, {%1, %1};" : "=l"(r) : "f"(v));
    return r;
}
__device__ __forceinline__ float2 unpack2(unsigned long long v) {
    float2 r;
    asm("mov.b64 {%0, %1}, %2;" : "=f"(r.x), "=f"(r.y) : "l"(v));
    return r;
}
// unpack one uint4 = 8 halves (4 half2) and accumulate into 8 fp32
__device__ __forceinline__ void acc_h8(float* a, uint4 v) {
    const __half2* h = (const __half2*)&v;
#pragma unroll
    for (int i = 0; i < 4; i++) {
        float2 f = __half22float2(h[i]);
        a[2 * i]     += f.x;
        a[2 * i + 1] += f.y;
    }
}

// ---------------- CSR build (head) ------------------------------------------
__global__ void k_init() {
    int i = blockIdx.x * blockDim.x + threadIdx.x;
    if (i < N_NODES) g_cnt[i] = 0;
    if (i == 0) g_head = 0;
}

__global__ void k_cnt(const int* __restrict__ dst) {
    int e = blockIdx.x * blockDim.x + threadIdx.x;
    if (e < N_EDGES) atomicAdd(&g_cnt[dst[e]], 1);
}

__global__ void k_alloc() {
    int i = blockIdx.x * blockDim.x + threadIdx.x;
    if (i >= N_NODES) return;
    int c = g_cnt[i];
    int s = atomicAdd(&g_head, c);
    g_start[i]  = s;
    g_cursor[i] = s;
    g_dinv[i]   = rsqrtf((float)(c + 1));   // +1 self loop
}

// ---------------- fused: GEMM1 (f32x2, 8x4 microtile) + CSR-fill ------------
// blocks [0, GEMM1_BLOCKS)      : p1h = fp16(dinv .* (x @ W1))
// blocks [GEMM1_BLOCKS, +12500) : csr fill
__global__ __launch_bounds__(256) void k_gemm1_fill(const float* __restrict__ X,
                                                    const float* __restrict__ W,
                                                    const int* __restrict__ src,
                                                    const int* __restrict__ dst) {
    const int tid = threadIdx.x;

    if (blockIdx.x >= GEMM1_BLOCKS) {
        int e = (blockIdx.x - GEMM1_BLOCKS) * 256 + tid;
        if (e < N_EDGES) {
            int d = dst[e];
            int pos = atomicAdd(&g_cursor[d], 1);
            g_csr[pos] = src[e];
        }
        return;
    }

    // ---- GEMM1: 128x64 tile, 8m x 4n microtile (m in f32x2 pairs), BK=16 ----
    __shared__ float Xs[16][132];   // [k][m] padded
    __shared__ float Ws[16][64];    // [k][n]
    const int tx = tid & 15;
    const int ty = tid >> 4;
    const int blockM = blockIdx.x * 128;

    unsigned long long acc2[4][4] = {};   // [m-pair][n]

    for (int k0 = 0; k0 < K1; k0 += 16) {
#pragma unroll
        for (int i = 0; i < 8; i++) {
            int e  = tid + i * 256;
            int kl = e & 15, ml = e >> 4;
            int r = blockM + ml, k = k0 + kl;
            Xs[kl][ml] = (r < N_NODES && k < K1) ? X[(long long)r * K1 + k] : 0.f;
        }
        {
            int kl = tid >> 4, nl = (tid & 15) * 4;
            int k = k0 + kl;
            float4 w = (k < K1) ? *(const float4*)&W[k * 64 + nl]
                                : make_float4(0.f, 0.f, 0.f, 0.f);
            *(float4*)&Ws[kl][nl] = w;
        }
        __syncthreads();
#pragma unroll
        for (int kk = 0; kk < 16; kk++) {
            unsigned long long xp[4];
            *(float4*)&xp[0] = *(const float4*)&Xs[kk][ty * 8];
            *(float4*)&xp[2] = *(const float4*)&Xs[kk][ty * 8 + 4];
            float4 wv = *(const float4*)&Ws[kk][tx * 4];
            unsigned long long ws0 = splat2(wv.x), ws1 = splat2(wv.y);
            unsigned long long ws2 = splat2(wv.z), ws3 = splat2(wv.w);
#pragma unroll
            for (int ip = 0; ip < 4; ip++) {
                fma2(acc2[ip][0], xp[ip], ws0);
                fma2(acc2[ip][1], xp[ip], ws1);
                fma2(acc2[ip][2], xp[ip], ws2);
                fma2(acc2[ip][3], xp[ip], ws3);
            }
        }
        __syncthreads();
    }

    // epilogue: unpack m-pairs, scale by dinv, convert fp16, store 4 cols
#pragma unroll
    for (int ip = 0; ip < 4; ip++) {
        int r0 = blockM + ty * 8 + ip * 2;
        int r1 = r0 + 1;
        float2 c0 = unpack2(acc2[ip][0]);
        float2 c1 = unpack2(acc2[ip][1]);
        float2 c2 = unpack2(acc2[ip][2]);
        float2 c3 = unpack2(acc2[ip][3]);
        if (r0 < N_NODES) {
            float s = g_dinv[r0];
            __half2 h[2];
            h[0] = __floats2half2_rn(c0.x * s, c1.x * s);
            h[1] = __floats2half2_rn(c2.x * s, c3.x * s);
            *(uint2*)&g_p1h[(long long)r0 * 64 + tx * 4] = *(uint2*)h;
        }
        if (r1 < N_NODES) {
            float s = g_dinv[r1];
            __half2 h[2];
            h[0] = __floats2half2_rn(c0.y * s, c1.y * s);
            h[1] = __floats2half2_rn(c2.y * s, c3.y * s);
            *(uint2*)&g_p1h[(long long)r1 * 64 + tx * 4] = *(uint2*)h;
        }
    }
}

// ---------------- fused gather64 + GEMM2 (smem-staged) -----------------------
// Phase 1: 32 nodes/block, 8 lanes/node aggregate into smem sA[32][68].
// Phase 2: warp w computes gemm2 for node slots {w, w+8, w+16, w+24} using
// the proven warp-broadcast shuffle loop, reading activations from smem.
__global__ __launch_bounds__(256) void k_gather64_gemm2(const float* __restrict__ W2,
                                                        const float* __restrict__ b1) {
    __shared__ float Ws2[64 * 32];
    __shared__ float bs[64];
    __shared__ float sA[32][68];    // padded rows (272B, 16B-aligned)

    const int tid = threadIdx.x;
    for (int i = tid; i < 64 * 32; i += 256) Ws2[i] = W2[i];
    if (tid < 64) bs[tid] = b1[tid];

    // ---- phase 1: gather (identical to proven k_gather64) ----
    const int slot = tid >> 3, g = tid & 7;
    const int node = blockIdx.x * 32 + slot;          // grid exact: no tail
    const uint4* P = (const uint4*)g_p1h;             // 8 uint4 per node row

    float a[8] = {};
    acc_h8(a, P[node * 8 + g]);                       // self loop
    int beg = g_start[node], n = g_cnt[node];
    int j = 0;
    for (; j + 4 <= n; j += 4) {
        int s0 = g_csr[beg + j],     s1 = g_csr[beg + j + 1];
        int s2 = g_csr[beg + j + 2], s3 = g_csr[beg + j + 3];
        uint4 u0 = __ldg(P + s0 * 8 + g);
        uint4 u1 = __ldg(P + s1 * 8 + g);
        uint4 u2 = __ldg(P + s2 * 8 + g);
        uint4 u3 = __ldg(P + s3 * 8 + g);
        acc_h8(a, u0); acc_h8(a, u1); acc_h8(a, u2); acc_h8(a, u3);
    }
    for (; j < n; j++)
        acc_h8(a, __ldg(P + g_csr[beg + j] * 8 + g));

    *(float4*)&sA[slot][g * 8]     = make_float4(a[0], a[1], a[2], a[3]);
    *(float4*)&sA[slot][g * 8 + 4] = make_float4(a[4], a[5], a[6], a[7]);

    __syncthreads();

    // ---- phase 2: gemm2 (warp-broadcast shuffles, constant indices) ----
    const int warp = tid >> 5, lane = tid & 31;
#pragma unroll
    for (int it = 0; it < 4; it++) {
        int s = warp + it * 8;                        // node slot 0..31
        int row = blockIdx.x * 32 + s;
        float dv = g_dinv[row];
        float r0 = fmaxf(fmaf(dv, sA[s][lane],      bs[lane]),      0.f);
        float r1 = fmaxf(fmaf(dv, sA[s][lane + 32], bs[lane + 32]), 0.f);
        float acc = 0.f;
#pragma unroll
        for (int k = 0; k < 32; k++) {
            float xv = __shfl_sync(0xffffffffu, r0, k);
            acc = fmaf(xv, Ws2[k * 32 + lane], acc);
        }
#pragma unroll
        for (int k = 0; k < 32; k++) {
            float xv = __shfl_sync(0xffffffffu, r1, k);
            acc = fmaf(xv, Ws2[(k + 32) * 32 + lane], acc);
        }
        g_p2h[(long long)row * 32 + lane] = __float2half(acc * dv);
    }
}

// ---------------- fused gather32 (fp16 msgs) + GEMM3 ------------------------
// 4 lanes per node; each lane owns one uint4 = 8 features.
__global__ __launch_bounds__(256) void k_gather32_gemm3(const float* __restrict__ W3,
                                                        const float* __restrict__ b2) {
    __shared__ float w3[64];
    __shared__ float bb[32];
    if (threadIdx.x < 64) w3[threadIdx.x] = W3[threadIdx.x];
    if (threadIdx.x < 32) bb[threadIdx.x] = b2[threadIdx.x];
    __syncthreads();

    int t = blockIdx.x * blockDim.x + threadIdx.x;
    int node = t >> 2, lane = t & 3;
    if (node >= N_NODES) return;
    const uint4* P = (const uint4*)g_p2h;   // 4 uint4 per node row

    float a[8] = {};
    acc_h8(a, P[node * 4 + lane]);          // self loop
    int beg = g_start[node], n = g_cnt[node];
    int j = 0;
    for (; j + 4 <= n; j += 4) {
        int s0 = g_csr[beg + j],     s1 = g_csr[beg + j + 1];
        int s2 = g_csr[beg + j + 2], s3 = g_csr[beg + j + 3];
        uint4 u0 = __ldg(P + s0 * 4 + lane);
        uint4 u1 = __ldg(P + s1 * 4 + lane);
        uint4 u2 = __ldg(P + s2 * 4 + lane);
        uint4 u3 = __ldg(P + s3 * 4 + lane);
        acc_h8(a, u0); acc_h8(a, u1); acc_h8(a, u2); acc_h8(a, u3);
    }
    for (; j < n; j++)
        acc_h8(a, __ldg(P + g_csr[beg + j] * 4 + lane));

    float dv = g_dinv[node];
    int kb = lane * 8;
    float acc0 = 0.f, acc1 = 0.f;
#pragma unroll
    for (int i = 0; i < 8; i++) {
        float h = fmaxf(fmaf(dv, a[i], bb[kb + i]), 0.f);
        acc0 = fmaf(h, w3[(kb + i) * 2],     acc0);
        acc1 = fmaf(h, w3[(kb + i) * 2 + 1], acc1);
    }
#pragma unroll
    for (int off = 2; off > 0; off >>= 1) {
        acc0 += __shfl_down_sync(0xffffffffu, acc0, off, 4);
        acc1 += __shfl_down_sync(0xffffffffu, acc1, off, 4);
    }
    if (lane == 0)
        ((float2*)g_p3)[node] = make_float2(acc0 * dv, acc1 * dv);
}

// ---------------- fused gather2 + log_softmax -------------------------------
__global__ __launch_bounds__(256) void k_gather2_out(const float* __restrict__ b3,
                                                     float* __restrict__ out) {
    int node = blockIdx.x * blockDim.x + threadIdx.x;
    if (node >= N_NODES) return;
    const float2* P = (const float2*)g_p3;
    float2 v = P[node];   // self loop
    int beg = g_start[node], n = g_cnt[node];
    int j = 0;
    for (; j + 4 <= n; j += 4) {
        int s0 = g_csr[beg + j],     s1 = g_csr[beg + j + 1];
        int s2 = g_csr[beg + j + 2], s3 = g_csr[beg + j + 3];
        float2 u0 = __ldg(P + s0), u1 = __ldg(P + s1);
        float2 u2 = __ldg(P + s2), u3 = __ldg(P + s3);
        v.x += (u0.x + u1.x) + (u2.x + u3.x);
        v.y += (u0.y + u1.y) + (u2.y + u3.y);
    }
    for (; j < n; j++) {
        float2 u = __ldg(P + g_csr[beg + j]);
        v.x += u.x; v.y += u.y;
    }
    float dv = g_dinv[node];
    float z0 = fmaf(dv, v.x, __ldg(&b3[0]));
    float z1 = fmaf(dv, v.y, __ldg(&b3[1]));
    float m = fmaxf(z0, z1);
    float lse = m + logf(expf(z0 - m) + expf(z1 - m));
    ((float2*)out)[node] = make_float2(z0 - lse, z1 - lse);
}

// ---------------- launch ----------------------------------------------------
extern "C" void kernel_launch(void* const* d_in, const int* in_sizes, int n_in,
                              void* d_out, int out_size) {
    const float* x  = (const float*)d_in[0];
    const int*   ei = (const int*)d_in[1];
    const float* W1 = (const float*)d_in[2];
    const float* b1 = (const float*)d_in[3];
    const float* W2 = (const float*)d_in[4];
    const float* b2 = (const float*)d_in[5];
    const float* W3 = (const float*)d_in[6];
    const float* b3 = (const float*)d_in[7];
    float* out = (float*)d_out;

    const int* src = ei;
    const int* dst = ei + N_EDGES;

    const int TB = 256;
    const int gN = (N_NODES + TB - 1) / TB;
    const int gE = (N_EDGES + TB - 1) / TB;   // 12500

    // CSR head
    k_init<<<gN, TB>>>();
    k_cnt<<<gE, TB>>>(dst);
    k_alloc<<<gN, TB>>>();

    // layer 1 GEMM (f32x2) overlapped with CSR fill
    k_gemm1_fill<<<GEMM1_BLOCKS + gE, TB>>>(x, W1, src, dst);

    // layer 1 aggregation + layer 2 GEMM (smem-fused)
    k_gather64_gemm2<<<N_NODES / 32, TB>>>(W2, b1);   // 3125 blocks, exact

    // layer 3 (gather32 + gemm3 fused, fp16 messages)
    k_gather32_gemm3<<<(N_NODES * 4 + TB - 1) / TB, TB>>>(W3, b2);

    // output (gather2 + log_softmax fused)
    k_gather2_out<<<gN, TB>>>(b3, out);
}